// round 1
// baseline (speedup 1.0000x reference)
#include <cuda_runtime.h>
#include <cuda_bf16.h>
#include <math.h>

#define Bb 16
#define Ll 512
#define Dd 512
#define Nn 3
#define Hh 8
#define DH 64
#define AH 256
#define KHALF 7   // ksize 15 -> 7 each side

// ---------------- scratch (device globals; no allocation in kernel_launch) ----
__device__ float g_H2 [Bb*Nn*Dd];              // relu(se @ w2 + b2)
__device__ float g_B1 [(long)Nn*Bb*Ll*Dd];     // relu(seg @ w1 + b1) * h2
__device__ float g_M  [(long)Nn*Bb*Ll*Dd];     // m, then ss after local NLs (layout [n][b][l][d])
__device__ float g_CT [(long)Bb*Ll*2*Dd];      // ct = x @ cW + cb   (mq | mv)
__device__ float g_MK [(long)Bb*Ll*Dd];        // mk = x @ vW + vb
__device__ float g_A  [(long)Bb*Ll*Dd];        // aggregated a (residual-updated)
__device__ float g_S  [(long)Bb*Hh*Ll*Ll];     // global attention scores
__device__ float g_SW [Bb*Nn];                 // sattw

// ---------------- generic tiled fp32 GEMM -------------------------------------
// C[z] = act( alpha * A[z] @ op(B[z]) + bias ) (+ C if beta1)
// flags: 1 = transB (B is N x K row-major, use B^T), 2 = relu, 4 = beta1 (accumulate)
// batch offset for P in {A,B,C}: (z / zInner)*sPo + (z % zInner)*sPi
#define BM 64
#define BN 64
#define BK 16

__global__ void gemm_k(const float* __restrict__ A, const float* __restrict__ Bm,
                       const float* __restrict__ bias, float* __restrict__ C,
                       int M, int N, int K, int lda, int ldb, int ldc,
                       int zInner,
                       long sAo, long sAi, long sBo, long sBi, long sCo, long sCi,
                       float alpha, int flags)
{
    int z  = blockIdx.z;
    int zo = z / zInner, zi = z % zInner;
    A  += zo * sAo + zi * sAi;
    Bm += zo * sBo + zi * sBi;
    C  += zo * sCo + zi * sCi;

    __shared__ float As[BK][BM + 4];
    __shared__ float Bs[BK][BN + 4];

    int tid = threadIdx.x;
    int tx = tid & 15, ty = tid >> 4;
    int m0 = blockIdx.y * BM, n0 = blockIdx.x * BN;
    bool tb = (flags & 1);

    float acc[4][4] = {};

    for (int k0 = 0; k0 < K; k0 += BK) {
        #pragma unroll
        for (int i = 0; i < 4; i++) {                // A tile 64x16
            int idx = tid + i * 256;
            int m = idx >> 4, k = idx & 15;
            As[k][m] = A[(long)(m0 + m) * lda + (k0 + k)];
        }
        #pragma unroll
        for (int i = 0; i < 4; i++) {                // B tile 16x64
            int idx = tid + i * 256;
            if (!tb) { int k = idx >> 6, n = idx & 63; Bs[k][n] = Bm[(long)(k0 + k) * ldb + (n0 + n)]; }
            else     { int n = idx >> 4, k = idx & 15; Bs[k][n] = Bm[(long)(n0 + n) * ldb + (k0 + k)]; }
        }
        __syncthreads();
        #pragma unroll
        for (int k = 0; k < BK; k++) {
            float4 a4 = *reinterpret_cast<const float4*>(&As[k][ty * 4]);
            float4 b4 = *reinterpret_cast<const float4*>(&Bs[k][tx * 4]);
            float av[4] = {a4.x, a4.y, a4.z, a4.w};
            float bv[4] = {b4.x, b4.y, b4.z, b4.w};
            #pragma unroll
            for (int i = 0; i < 4; i++)
                #pragma unroll
                for (int j = 0; j < 4; j++)
                    acc[i][j] = fmaf(av[i], bv[j], acc[i][j]);
        }
        __syncthreads();
    }

    #pragma unroll
    for (int i = 0; i < 4; i++) {
        int m = m0 + ty * 4 + i;
        #pragma unroll
        for (int j = 0; j < 4; j++) {
            int n = n0 + tx * 4 + j;
            float v = acc[i][j] * alpha;
            if (bias) v += bias[n];
            if (flags & 2) v = fmaxf(v, 0.f);
            long ci = (long)m * ldc + n;
            if (flags & 4) v += C[ci];
            C[ci] = v;
        }
    }
}

// ---------------- small kernels ------------------------------------------------

// h2[b,n,h] = relu(se[b,n,:] @ w2[n,:,h] + b2[n,h])
__global__ void h2_k(const float* __restrict__ se, const float* __restrict__ w2,
                     const float* __restrict__ b2, float* __restrict__ H2o)
{
    int bn = blockIdx.x;               // b*Nn + n
    int n = bn % Nn;
    int h = threadIdx.x;               // 512
    const float* x = se + (long)bn * Dd;
    const float* w = w2 + (long)n * Dd * Dd;
    float acc = b2[n * Dd + h];
    for (int d = 0; d < Dd; d++) acc = fmaf(x[d], w[(long)d * Dd + h], acc);
    H2o[(long)bn * Dd + h] = fmaxf(acc, 0.f);
}

// g_B1[n,b,l,h] *= g_H2[b,n,h]
__global__ void mulh2_k()
{
    long total = (long)Nn * Bb * Ll * Dd;
    for (long i = (long)blockIdx.x * blockDim.x + threadIdx.x; i < total;
         i += (long)gridDim.x * blockDim.x) {
        int h = (int)(i % Dd);
        long r = i / Dd;
        int b = (int)((r / Ll) % Bb);
        int n = (int)(r / ((long)Ll * Bb));
        g_B1[i] *= g_H2[((long)b * Nn + n) * Dd + h];
    }
}

// banded local attention + residual, warp per (b,l,h)
__global__ void local_attn_k(const float* __restrict__ MK, const float* __restrict__ CT,
                             const float* __restrict__ mask, float* __restrict__ X)
{
    int gw = (int)(((long)blockIdx.x * blockDim.x + threadIdx.x) >> 5);
    int lane = threadIdx.x & 31;
    if (gw >= Bb * Ll * Hh) return;
    int h = gw % Hh;
    int l = (gw / Hh) % Ll;
    int b = gw / (Hh * Ll);

    const float* mkr = MK + ((long)b * Ll + l) * Dd + h * DH;
    float k0 = mkr[lane], k1 = mkr[lane + 32];

    float sc[15];
    #pragma unroll
    for (int j = 0; j < 15; j++) {
        int m = l + (j - KHALF);
        float s = -1e30f;
        if (m >= 0 && m < Ll && mask[(long)b * Ll + m] != 0.f) {
            const float* mq = CT + ((long)b * Ll + m) * (2 * Dd) + h * DH;
            float d = k0 * mq[lane] + k1 * mq[lane + 32];
            #pragma unroll
            for (int o = 16; o; o >>= 1) d += __shfl_xor_sync(0xffffffffu, d, o);
            s = d * 0.125f;             // 1/sqrt(64)
        }
        sc[j] = s;
    }
    float mx = -1e30f;
    #pragma unroll
    for (int j = 0; j < 15; j++) mx = fmaxf(mx, sc[j]);
    float w[15], sum = 0.f;
    #pragma unroll
    for (int j = 0; j < 15; j++) {
        w[j] = (sc[j] > -1e29f) ? expf(sc[j] - mx) : 0.f;
        sum += w[j];
    }
    float inv = 1.f / sum;
    float o0 = 0.f, o1 = 0.f;
    #pragma unroll
    for (int j = 0; j < 15; j++) {
        if (w[j] != 0.f) {
            int m = l + (j - KHALF);
            const float* mv = CT + ((long)b * Ll + m) * (2 * Dd) + Dd + h * DH;
            float ww = w[j] * inv;
            o0 = fmaf(ww, mv[lane], o0);
            o1 = fmaf(ww, mv[lane + 32], o1);
        }
    }
    float* xr = X + ((long)b * Ll + l) * Dd + h * DH;
    xr[lane]      += o0;
    xr[lane + 32] += o1;
}

// row softmax with segment mask; S layout (B,H,L,L); block (256) per row
__global__ void softmax_k(float* __restrict__ S, const float* __restrict__ mask)
{
    long row = blockIdx.x;                 // (b*H + h)*L + l
    int b = (int)(row / ((long)Hh * Ll));
    float* s = S + row * Ll;
    const float* mrow = mask + (long)b * Ll;
    int t = threadIdx.x;

    float v0 = (mrow[t]       != 0.f) ? s[t]       : -1e9f;
    float v1 = (mrow[t + 256] != 0.f) ? s[t + 256] : -1e9f;

    __shared__ float red[256];
    red[t] = fmaxf(v0, v1);
    __syncthreads();
    for (int o = 128; o; o >>= 1) { if (t < o) red[t] = fmaxf(red[t], red[t + o]); __syncthreads(); }
    float mx = red[0];
    __syncthreads();

    float e0 = expf(v0 - mx), e1 = expf(v1 - mx);
    red[t] = e0 + e1;
    __syncthreads();
    for (int o = 128; o; o >>= 1) { if (t < o) red[t] += red[t + o]; __syncthreads(); }
    float inv = 1.f / red[0];
    s[t] = e0 * inv;
    s[t + 256] = e1 * inv;
}

// segment attention weights: alpha = tanh(se @ w1) @ w2, softmax over n; writes g_SW and out tail
__global__ void satt_k(const float* __restrict__ se, const float* __restrict__ w1,
                       const float* __restrict__ w2, float* __restrict__ out_tail)
{
    int b = blockIdx.x, t = threadIdx.x;   // 256 threads
    __shared__ float red[256];
    __shared__ float alpha[Nn];
    for (int n = 0; n < Nn; n++) {
        const float* x = se + ((long)b * Nn + n) * Dd;
        float acc = 0.f;
        for (int d = 0; d < Dd; d++) acc = fmaf(x[d], w1[(long)d * AH + t], acc);
        red[t] = tanhf(acc) * w2[t];
        __syncthreads();
        for (int o = 128; o; o >>= 1) { if (t < o) red[t] += red[t + o]; __syncthreads(); }
        if (t == 0) alpha[n] = red[0];
        __syncthreads();
    }
    if (t == 0) {
        float mx = fmaxf(alpha[0], fmaxf(alpha[1], alpha[2]));
        float e[Nn], sum = 0.f;
        for (int n = 0; n < Nn; n++) { e[n] = expf(alpha[n] - mx); sum += e[n]; }
        for (int n = 0; n < Nn; n++) {
            float w = e[n] / sum;
            g_SW[b * Nn + n] = w;
            out_tail[b * Nn + n] = w;
        }
    }
}

// a[b,l,d] = sum_n sattw[b,n] * ss[n,b,l,d]
__global__ void agg_k()
{
    long total = (long)Bb * Ll * Dd;
    long stride = (long)Ll * Dd;
    for (long i = (long)blockIdx.x * blockDim.x + threadIdx.x; i < total;
         i += (long)gridDim.x * blockDim.x) {
        int b = (int)(i / stride);
        float acc = 0.f;
        #pragma unroll
        for (int n = 0; n < Nn; n++)
            acc = fmaf(g_SW[b * Nn + n], g_M[(long)n * Bb * Ll * Dd + i], acc);
        g_A[i] = acc;
    }
}

__global__ void copyout_k(float* __restrict__ out)
{
    long total = (long)Bb * Ll * Dd;
    for (long i = (long)blockIdx.x * blockDim.x + threadIdx.x; i < total;
         i += (long)gridDim.x * blockDim.x)
        out[i] = g_A[i];
}

// ---------------- host orchestration ------------------------------------------

static void launch_gemm(const float* A, const float* B, const float* bias, float* C,
                        int M, int N, int K, int lda, int ldb, int ldc,
                        int batches, int zInner,
                        long sAo, long sAi, long sBo, long sBi, long sCo, long sCi,
                        float alpha, int flags)
{
    dim3 grid(N / BN, M / BM, batches);
    gemm_k<<<grid, 256>>>(A, B, bias, C, M, N, K, lda, ldb, ldc,
                          zInner, sAo, sAi, sBo, sBi, sCo, sCi, alpha, flags);
}

extern "C" void kernel_launch(void* const* d_in, const int* in_sizes, int n_in,
                              void* d_out, int out_size)
{
    const float* seg   = (const float*)d_in[0];   // (B,L,D)
    const float* mask  = (const float*)d_in[1];   // (B,L)
    const float* se    = (const float*)d_in[2];   // (B,N,D)
    const float* hw1   = (const float*)d_in[3];   // (N,D,D)
    const float* hb1   = (const float*)d_in[4];   // (N,D)
    const float* hw2   = (const float*)d_in[5];
    const float* hb2   = (const float*)d_in[6];
    const float* hw3   = (const float*)d_in[7];
    const float* hb3   = (const float*)d_in[8];
    const float* lcW   = (const float*)d_in[9];   // (N,2,D,2D)
    const float* lcb   = (const float*)d_in[10];  // (N,2,2D)
    const float* lvW   = (const float*)d_in[11];  // (N,2,D,D)
    const float* lvb   = (const float*)d_in[12];  // (N,2,D)
    const float* gcW   = (const float*)d_in[13];  // (2,D,2D)
    const float* gcb   = (const float*)d_in[14];  // (2,2D)
    const float* gvW   = (const float*)d_in[15];  // (2,D,D)
    const float* gvb   = (const float*)d_in[16];  // (2,D)
    const float* sw1   = (const float*)d_in[17];  // (D,AH)
    const float* sw2   = (const float*)d_in[18];  // (AH,1)
    float* out = (float*)d_out;

    float *pH2, *pB1, *pM, *pCT, *pMK, *pA, *pS;
    cudaGetSymbolAddress((void**)&pH2, g_H2);
    cudaGetSymbolAddress((void**)&pB1, g_B1);
    cudaGetSymbolAddress((void**)&pM,  g_M);
    cudaGetSymbolAddress((void**)&pCT, g_CT);
    cudaGetSymbolAddress((void**)&pMK, g_MK);
    cudaGetSymbolAddress((void**)&pA,  g_A);
    cudaGetSymbolAddress((void**)&pS,  g_S);

    const long BLD = (long)Bb * Ll * Dd;
    const int  ML  = Bb * Ll;   // 8192 rows for flat (b,l) GEMMs

    // 1) h2
    h2_k<<<Bb * Nn, Dd>>>(se, hw2, hb2, pH2);

    // 2) h1 = relu(seg @ w1 + b1), per n
    for (int n = 0; n < Nn; n++)
        launch_gemm(seg, hw1 + (long)n * Dd * Dd, hb1 + n * Dd, pB1 + (long)n * BLD,
                    ML, Dd, Dd, Dd, Dd, Dd, 1, 1, 0, 0, 0, 0, 0, 0, 1.f, /*relu*/2);

    // 3) h1 *= h2
    mulh2_k<<<4096, 256>>>();

    // 4) m = relu(h1mul @ w3 + b3), per n
    for (int n = 0; n < Nn; n++)
        launch_gemm(pB1 + (long)n * BLD, hw3 + (long)n * Dd * Dd, hb3 + n * Dd,
                    pM + (long)n * BLD,
                    ML, Dd, Dd, Dd, Dd, Dd, 1, 1, 0, 0, 0, 0, 0, 0, 1.f, 2);

    // 5) local non-local blocks (banded attention), per n, per stage
    for (int n = 0; n < Nn; n++) {
        float* X = pM + (long)n * BLD;
        for (int s = 0; s < 2; s++) {
            int ns = n * 2 + s;
            launch_gemm(X, lcW + (long)ns * Dd * 2 * Dd, lcb + (long)ns * 2 * Dd, pCT,
                        ML, 2 * Dd, Dd, Dd, 2 * Dd, 2 * Dd, 1, 1, 0, 0, 0, 0, 0, 0, 1.f, 0);
            launch_gemm(X, lvW + (long)ns * Dd * Dd, lvb + (long)ns * Dd, pMK,
                        ML, Dd, Dd, Dd, Dd, Dd, 1, 1, 0, 0, 0, 0, 0, 0, 1.f, 0);
            int warps = Bb * Ll * Hh;
            local_attn_k<<<warps * 32 / 128, 128>>>(pMK, pCT, mask, X);
        }
    }

    // 6) segment attention weights (also writes out tail)
    satt_k<<<Bb, AH>>>(se, sw1, sw2, out + BLD);

    // 7) a = sum_n sattw * ss
    agg_k<<<4096, 256>>>();

    // 8) global non-local blocks (full attention)
    for (int s = 0; s < 2; s++) {
        launch_gemm(pA, gcW + (long)s * Dd * 2 * Dd, gcb + (long)s * 2 * Dd, pCT,
                    ML, 2 * Dd, Dd, Dd, 2 * Dd, 2 * Dd, 1, 1, 0, 0, 0, 0, 0, 0, 1.f, 0);
        launch_gemm(pA, gvW + (long)s * Dd * Dd, gvb + (long)s * Dd, pMK,
                    ML, Dd, Dd, Dd, Dd, Dd, 1, 1, 0, 0, 0, 0, 0, 0, 1.f, 0);
        // scores: S[b,h] = (mk_bh @ mq_bh^T) / 8       M=L, N=L, K=64
        launch_gemm(pMK, pCT, nullptr, pS,
                    Ll, Ll, DH, Dd, 2 * Dd, Ll,
                    Bb * Hh, Hh,
                    (long)Ll * Dd, DH,               // A: per-b, per-h
                    (long)Ll * 2 * Dd, DH,           // B: per-b, per-h
                    (long)Hh * Ll * Ll, (long)Ll * Ll,
                    0.125f, /*transB*/1);
        softmax_k<<<Bb * Hh * Ll, 256>>>(pS, mask);
        // out: X[b,:,h*64:(h+1)*64] += W[b,h] @ mv_bh   M=L, N=64, K=L
        launch_gemm(pS, pCT + Dd, nullptr, pA,
                    Ll, DH, Ll, Ll, 2 * Dd, Dd,
                    Bb * Hh, Hh,
                    (long)Hh * Ll * Ll, (long)Ll * Ll,
                    (long)Ll * 2 * Dd, DH,
                    (long)Ll * Dd, DH,
                    1.f, /*beta1*/4);
    }

    // 9) write a to output
    copyout_k<<<4096, 256>>>(out);
}

// round 3
// speedup vs baseline: 1.9293x; 1.9293x over previous
#include <cuda_runtime.h>
#include <cuda_bf16.h>
#include <math.h>
#include <stdint.h>

#define Bb 16
#define Ll 512
#define Dd 512
#define Nn 3
#define Hh 8
#define DH 64
#define AH 256
#define KHALF 7

// ---------------- scratch (device globals) -----------------------------------
__device__ float g_B1 [(long)Nn*Bb*Ll*Dd];
__device__ float g_M  [(long)Nn*Bb*Ll*Dd];     // m, then ss
__device__ float g_CT [(long)Nn*Bb*Ll*2*Dd];   // ct per n-slot
__device__ float g_MK [(long)Nn*Bb*Ll*Dd];     // mk per n-slot
__device__ float g_A  [(long)Bb*Ll*Dd];
__device__ float g_S  [(long)Bb*Hh*Ll*Ll];
__device__ float g_SW [Bb*Nn];
__device__ float g_H2 [Bb*Nn*Dd];

// ---------------- mma.sync helpers -------------------------------------------
__device__ __forceinline__ uint32_t smem_u32(const void* p) {
    uint32_t a;
    asm("{ .reg .u64 t; cvta.to.shared.u64 t, %1; cvt.u32.u64 %0, t; }" : "=r"(a) : "l"(p));
    return a;
}
#define LDM_X4(r, a) asm volatile( \
    "ldmatrix.sync.aligned.m8n8.x4.shared.b16 {%0,%1,%2,%3}, [%4];" \
    : "=r"((r)[0]),"=r"((r)[1]),"=r"((r)[2]),"=r"((r)[3]) : "r"(a))
#define LDM_X4T(r, a) asm volatile( \
    "ldmatrix.sync.aligned.m8n8.x4.trans.shared.b16 {%0,%1,%2,%3}, [%4];" \
    : "=r"((r)[0]),"=r"((r)[1]),"=r"((r)[2]),"=r"((r)[3]) : "r"(a))
#define MMA16816(d, a, b) asm volatile( \
    "mma.sync.aligned.m16n8k16.row.col.f32.bf16.bf16.f32 " \
    "{%0,%1,%2,%3}, {%4,%5,%6,%7}, {%8,%9}, {%0,%1,%2,%3};" \
    : "+f"((d)[0]),"+f"((d)[1]),"+f"((d)[2]),"+f"((d)[3]) \
    : "r"((a)[0]),"r"((a)[1]),"r"((a)[2]),"r"((a)[3]), "r"((b)[0]),"r"((b)[1]))

__device__ __forceinline__ uint32_t pack_bf(__nv_bfloat16 a, __nv_bfloat16 b) {
    uint16_t ua = *reinterpret_cast<uint16_t*>(&a);
    uint16_t ub = *reinterpret_cast<uint16_t*>(&b);
    return (uint32_t)ua | ((uint32_t)ub << 16);
}
__device__ __forceinline__ void split4(float4 v, uint2& hp, uint2& lp,
                                       __nv_bfloat16* h, __nv_bfloat16* l) {
    h[0] = __float2bfloat16(v.x); l[0] = __float2bfloat16(v.x - __bfloat162float(h[0]));
    h[1] = __float2bfloat16(v.y); l[1] = __float2bfloat16(v.y - __bfloat162float(h[1]));
    h[2] = __float2bfloat16(v.z); l[2] = __float2bfloat16(v.z - __bfloat162float(h[2]));
    h[3] = __float2bfloat16(v.w); l[3] = __float2bfloat16(v.w - __bfloat162float(h[3]));
    hp.x = pack_bf(h[0], h[1]); hp.y = pack_bf(h[2], h[3]);
    lp.x = pack_bf(l[0], l[1]); lp.y = pack_bf(l[2], l[3]);
}

// ---------------- generic bf16-split mma.sync GEMM ----------------------------
// C = act( alpha * A @ op(B) + bias ) (+C if beta1)
// flags: 1=transB (B is [N][K]), 2=relu, 4=accumulate
template<int BN_T>
__global__ void __launch_bounds__(256, 1) mma_gemm_k(
    const float* __restrict__ Ag, const float* __restrict__ Bg,
    const float* __restrict__ bias, float* __restrict__ Cg,
    int K, int lda, int ldb, int ldc, int zInner,
    long sAo, long sAi, long sBo, long sBi, long sCo, long sCi, long sBias,
    float alpha, int flags)
{
    constexpr int BM = 128, BK = 32, LDS = 40;
    constexpr int LDSB = BN_T + 8;               // !tb layout row stride
    constexpr int WN = BN_T / 4;
    constexpr int NT = WN / 8;
    constexpr int MT = 4;
    constexpr int AIT = BM * BK / 1024;          // 4
    constexpr int BIT = BN_T * BK / 1024;        // 4 or 2
    constexpr int A_BYTES = BM * LDS * 2;        // 10240
    constexpr int B_ELEM  = (BN_T * LDS > BK * LDSB) ? BN_T * LDS : BK * LDSB;
    constexpr int B_BYTES = B_ELEM * 2;
    constexpr int STAGE = 2 * A_BYTES + 2 * B_BYTES;

    extern __shared__ char dsm[];

    int z = blockIdx.z, zo = z / zInner, zi = z % zInner;
    Ag += zo * sAo + zi * sAi;
    Bg += zo * sBo + zi * sBi;
    Cg += zo * sCo + zi * sCi;
    if (bias) bias += zi * sBias;

    int tid = threadIdx.x, lane = tid & 31, wid = tid >> 5;
    int wm = wid & 1, wn = wid >> 1;
    int m0 = blockIdx.y * BM, n0 = blockIdx.x * BN_T;
    const bool tb = flags & 1;

    float acc[MT][NT][4];
    #pragma unroll
    for (int i = 0; i < MT; i++)
        #pragma unroll
        for (int j = 0; j < NT; j++)
            #pragma unroll
            for (int e = 0; e < 4; e++) acc[i][j][e] = 0.f;

    float4 ar[AIT], br[BIT];

    auto loadT = [&](int k0) {
        #pragma unroll
        for (int it = 0; it < AIT; it++) {
            int idx = tid * 4 + it * 1024;
            int row = idx >> 5, kk = idx & 31;
            ar[it] = *reinterpret_cast<const float4*>(Ag + (long)(m0 + row) * lda + k0 + kk);
        }
        if (!tb) {
            #pragma unroll
            for (int it = 0; it < BIT; it++) {
                int idx = tid * 4 + it * 1024;
                int kk = idx / BN_T, nn = idx % BN_T;
                br[it] = *reinterpret_cast<const float4*>(Bg + (long)(k0 + kk) * ldb + n0 + nn);
            }
        } else {
            #pragma unroll
            for (int it = 0; it < BIT; it++) {
                int idx = tid * 4 + it * 1024;
                int nn = idx >> 5, kk = idx & 31;
                br[it] = *reinterpret_cast<const float4*>(Bg + (long)(n0 + nn) * ldb + k0 + kk);
            }
        }
    };

    auto storeT = [&](int s) {
        char* st = dsm + s * STAGE;
        __nv_bfloat16* Ahi = (__nv_bfloat16*)st;
        __nv_bfloat16* Alo = (__nv_bfloat16*)(st + A_BYTES);
        __nv_bfloat16* Bhi = (__nv_bfloat16*)(st + 2 * A_BYTES);
        __nv_bfloat16* Blo = (__nv_bfloat16*)(st + 2 * A_BYTES + B_BYTES);
        __nv_bfloat16 h[4], l[4];
        uint2 hp, lp;
        #pragma unroll
        for (int it = 0; it < AIT; it++) {
            int idx = tid * 4 + it * 1024;
            int row = idx >> 5, kk = idx & 31;
            split4(ar[it], hp, lp, h, l);
            *reinterpret_cast<uint2*>(&Ahi[row * LDS + kk]) = hp;
            *reinterpret_cast<uint2*>(&Alo[row * LDS + kk]) = lp;
        }
        if (!tb) {
            #pragma unroll
            for (int it = 0; it < BIT; it++) {
                int idx = tid * 4 + it * 1024;
                int kk = idx / BN_T, nn = idx % BN_T;
                split4(br[it], hp, lp, h, l);
                *reinterpret_cast<uint2*>(&Bhi[kk * LDSB + nn]) = hp;
                *reinterpret_cast<uint2*>(&Blo[kk * LDSB + nn]) = lp;
            }
        } else {
            #pragma unroll
            for (int it = 0; it < BIT; it++) {
                int idx = tid * 4 + it * 1024;
                int nn = idx >> 5, kk = idx & 31;
                split4(br[it], hp, lp, h, l);
                *reinterpret_cast<uint2*>(&Bhi[nn * LDS + kk]) = hp;
                *reinterpret_cast<uint2*>(&Blo[nn * LDS + kk]) = lp;
            }
        }
    };

    int nc = K / BK;
    loadT(0);
    storeT(0);
    __syncthreads();

    uint32_t sb0 = smem_u32(dsm);
    // A ldmatrix lane offsets (non-trans)
    int alr = lane & 15, alc = (lane >> 4) << 3;
    // B non-trans (tb path): rows = n, cols = k
    int blr = (lane & 7) + (((lane >> 4) & 1) << 3);
    int blc = ((lane >> 3) & 1) << 3;
    // B trans (!tb path): rows = k, cols = n
    int btr = (lane & 7) + (((lane >> 3) & 1) << 3);
    int btc = ((lane >> 4) & 1) << 3;

    for (int c = 0; c < nc; c++) {
        if (c + 1 < nc) loadT((c + 1) * BK);
        int s = c & 1;
        uint32_t base = sb0 + s * STAGE;
        uint32_t aAhi = base + ((wm * 64 + alr) * LDS + alc) * 2;

        #pragma unroll
        for (int kk = 0; kk < 2; kk++) {
            uint32_t ah[MT][4], al[MT][4], bh[NT][2], bl[NT][2];
            #pragma unroll
            for (int mt = 0; mt < MT; mt++) {
                uint32_t o = (uint32_t)((mt * 16 * LDS + kk * 16) * 2);
                LDM_X4(ah[mt], aAhi + o);
                LDM_X4(al[mt], aAhi + A_BYTES + o);
            }
            if (!tb) {
                uint32_t aB = base + 2 * A_BYTES +
                              (uint32_t)(((kk * 16 + btr) * LDSB + wn * WN + btc) * 2);
                #pragma unroll
                for (int p = 0; p < NT / 2; p++) {
                    uint32_t o = (uint32_t)(p * 16 * 2);
                    uint32_t r[4];
                    LDM_X4T(r, aB + o);
                    bh[2*p][0]=r[0]; bh[2*p][1]=r[1]; bh[2*p+1][0]=r[2]; bh[2*p+1][1]=r[3];
                    LDM_X4T(r, aB + B_BYTES + o);
                    bl[2*p][0]=r[0]; bl[2*p][1]=r[1]; bl[2*p+1][0]=r[2]; bl[2*p+1][1]=r[3];
                }
            } else {
                uint32_t aB = base + 2 * A_BYTES +
                              (uint32_t)(((wn * WN + blr) * LDS + kk * 16 + blc) * 2);
                #pragma unroll
                for (int p = 0; p < NT / 2; p++) {
                    uint32_t o = (uint32_t)(p * 16 * LDS * 2);
                    uint32_t r[4];
                    LDM_X4(r, aB + o);
                    bh[2*p][0]=r[0]; bh[2*p][1]=r[1]; bh[2*p+1][0]=r[2]; bh[2*p+1][1]=r[3];
                    LDM_X4(r, aB + B_BYTES + o);
                    bl[2*p][0]=r[0]; bl[2*p][1]=r[1]; bl[2*p+1][0]=r[2]; bl[2*p+1][1]=r[3];
                }
            }
            #pragma unroll
            for (int mt = 0; mt < MT; mt++)
                #pragma unroll
                for (int nt = 0; nt < NT; nt++) {
                    MMA16816(acc[mt][nt], ah[mt], bh[nt]);
                    MMA16816(acc[mt][nt], ah[mt], bl[nt]);
                    MMA16816(acc[mt][nt], al[mt], bh[nt]);
                }
        }
        if (c + 1 < nc) storeT(1 - s);
        __syncthreads();
    }

    // ---- epilogue
    #pragma unroll
    for (int mt = 0; mt < MT; mt++) {
        int row = m0 + wm * 64 + mt * 16 + (lane >> 2);
        #pragma unroll
        for (int nt = 0; nt < NT; nt++) {
            int col = n0 + wn * WN + nt * 8 + (lane & 3) * 2;
            float d0 = acc[mt][nt][0] * alpha, d1 = acc[mt][nt][1] * alpha;
            float d2 = acc[mt][nt][2] * alpha, d3 = acc[mt][nt][3] * alpha;
            if (bias) {
                float b0 = bias[col], b1 = bias[col + 1];
                d0 += b0; d1 += b1; d2 += b0; d3 += b1;
            }
            if (flags & 2) {
                d0 = fmaxf(d0, 0.f); d1 = fmaxf(d1, 0.f);
                d2 = fmaxf(d2, 0.f); d3 = fmaxf(d3, 0.f);
            }
            long o0 = (long)row * ldc + col;
            long o1 = (long)(row + 8) * ldc + col;
            if (flags & 4) {
                float2 c0 = *reinterpret_cast<float2*>(Cg + o0);
                float2 c1 = *reinterpret_cast<float2*>(Cg + o1);
                d0 += c0.x; d1 += c0.y; d2 += c1.x; d3 += c1.y;
            }
            *reinterpret_cast<float2*>(Cg + o0) = make_float2(d0, d1);
            *reinterpret_cast<float2*>(Cg + o1) = make_float2(d2, d3);
        }
    }
}

// ---------------- small kernels ------------------------------------------------
__global__ void h2_k(const float* __restrict__ se, const float* __restrict__ w2,
                     const float* __restrict__ b2)
{
    int bn = blockIdx.x;
    int n = bn % Nn;
    int h = threadIdx.x;
    const float* x = se + (long)bn * Dd;
    const float* w = w2 + (long)n * Dd * Dd;
    float acc = b2[n * Dd + h];
    for (int d = 0; d < Dd; d++) acc = fmaf(x[d], w[(long)d * Dd + h], acc);
    g_H2[(long)bn * Dd + h] = fmaxf(acc, 0.f);
}

__global__ void mulh2_k()
{
    long total = (long)Nn * Bb * Ll * Dd;
    for (long i = (long)blockIdx.x * blockDim.x + threadIdx.x; i < total;
         i += (long)gridDim.x * blockDim.x) {
        int h = (int)(i % Dd);
        long r = i / Dd;
        int b = (int)((r / Ll) % Bb);
        int n = (int)(r / ((long)Ll * Bb));
        g_B1[i] *= g_H2[((long)b * Nn + n) * Dd + h];
    }
}

// banded local attention + residual; covers all n-slots; warp per (n,b,l,h)
__global__ void local_attn_k(const float* __restrict__ mask)
{
    const long BLD = (long)Bb * Ll * Dd;
    int gw = (int)(((long)blockIdx.x * blockDim.x + threadIdx.x) >> 5);
    int lane = threadIdx.x & 31;
    if (gw >= Nn * Bb * Ll * Hh) return;
    int h = gw % Hh;
    int l = (gw / Hh) % Ll;
    int b = (gw / (Hh * Ll)) % Bb;
    int n = gw / (Hh * Ll * Bb);

    const float* MK = g_MK + (long)n * BLD;
    const float* CT = g_CT + (long)n * 2 * BLD;
    float* X = g_M + (long)n * BLD;

    const float* mkr = MK + ((long)b * Ll + l) * Dd + h * DH;
    float k0 = mkr[lane], k1 = mkr[lane + 32];

    float sc[15];
    #pragma unroll
    for (int j = 0; j < 15; j++) {
        int m = l + (j - KHALF);
        float s = -1e30f;
        if (m >= 0 && m < Ll && mask[(long)b * Ll + m] != 0.f) {
            const float* mq = CT + ((long)b * Ll + m) * (2 * Dd) + h * DH;
            float d = k0 * mq[lane] + k1 * mq[lane + 32];
            #pragma unroll
            for (int o = 16; o; o >>= 1) d += __shfl_xor_sync(0xffffffffu, d, o);
            s = d * 0.125f;
        }
        sc[j] = s;
    }
    float mx = -1e30f;
    #pragma unroll
    for (int j = 0; j < 15; j++) mx = fmaxf(mx, sc[j]);
    float w[15], sum = 0.f;
    #pragma unroll
    for (int j = 0; j < 15; j++) {
        w[j] = (sc[j] > -1e29f) ? expf(sc[j] - mx) : 0.f;
        sum += w[j];
    }
    float inv = 1.f / sum;
    float o0 = 0.f, o1 = 0.f;
    #pragma unroll
    for (int j = 0; j < 15; j++) {
        if (w[j] != 0.f) {
            int m = l + (j - KHALF);
            const float* mv = CT + ((long)b * Ll + m) * (2 * Dd) + Dd + h * DH;
            float ww = w[j] * inv;
            o0 = fmaf(ww, mv[lane], o0);
            o1 = fmaf(ww, mv[lane + 32], o1);
        }
    }
    float* xr = X + ((long)b * Ll + l) * Dd + h * DH;
    xr[lane]      += o0;
    xr[lane + 32] += o1;
}

__global__ void softmax_k(float* __restrict__ S, const float* __restrict__ mask)
{
    long row = blockIdx.x;
    int b = (int)(row / ((long)Hh * Ll));
    float* s = S + row * Ll;
    const float* mrow = mask + (long)b * Ll;
    int t = threadIdx.x;

    float v0 = (mrow[t]       != 0.f) ? s[t]       : -1e9f;
    float v1 = (mrow[t + 256] != 0.f) ? s[t + 256] : -1e9f;

    __shared__ float red[256];
    red[t] = fmaxf(v0, v1);
    __syncthreads();
    for (int o = 128; o; o >>= 1) { if (t < o) red[t] = fmaxf(red[t], red[t + o]); __syncthreads(); }
    float mx = red[0];
    __syncthreads();

    float e0 = expf(v0 - mx), e1 = expf(v1 - mx);
    red[t] = e0 + e1;
    __syncthreads();
    for (int o = 128; o; o >>= 1) { if (t < o) red[t] += red[t + o]; __syncthreads(); }
    float inv = 1.f / red[0];
    s[t] = e0 * inv;
    s[t + 256] = e1 * inv;
}

__global__ void satt_k(const float* __restrict__ se, const float* __restrict__ w1,
                       const float* __restrict__ w2, float* __restrict__ out_tail)
{
    int b = blockIdx.x, t = threadIdx.x;
    __shared__ float red[256];
    __shared__ float alpha[Nn];
    for (int n = 0; n < Nn; n++) {
        const float* x = se + ((long)b * Nn + n) * Dd;
        float acc = 0.f;
        for (int d = 0; d < Dd; d++) acc = fmaf(x[d], w1[(long)d * AH + t], acc);
        red[t] = tanhf(acc) * w2[t];
        __syncthreads();
        for (int o = 128; o; o >>= 1) { if (t < o) red[t] += red[t + o]; __syncthreads(); }
        if (t == 0) alpha[n] = red[0];
        __syncthreads();
    }
    if (t == 0) {
        float mx = fmaxf(alpha[0], fmaxf(alpha[1], alpha[2]));
        float e[Nn], sum = 0.f;
        for (int n = 0; n < Nn; n++) { e[n] = expf(alpha[n] - mx); sum += e[n]; }
        for (int n = 0; n < Nn; n++) {
            float w = e[n] / sum;
            g_SW[b * Nn + n] = w;
            out_tail[b * Nn + n] = w;
        }
    }
}

__global__ void agg_k()
{
    long total = (long)Bb * Ll * Dd;
    long stride = (long)Ll * Dd;
    for (long i = (long)blockIdx.x * blockDim.x + threadIdx.x; i < total;
         i += (long)gridDim.x * blockDim.x) {
        int b = (int)(i / stride);
        float acc = 0.f;
        #pragma unroll
        for (int n = 0; n < Nn; n++)
            acc = fmaf(g_SW[b * Nn + n], g_M[(long)n * Bb * Ll * Dd + i], acc);
        g_A[i] = acc;
    }
}

__global__ void copyout_k(float* __restrict__ out)
{
    long total = (long)Bb * Ll * Dd;
    for (long i = (long)blockIdx.x * blockDim.x + threadIdx.x; i < total;
         i += (long)gridDim.x * blockDim.x)
        out[i] = g_A[i];
}

// ---------------- host orchestration ------------------------------------------
static void mgemm(int BN, const float* A, const float* B, const float* bias, float* C,
                  int M, int N, int K, int lda, int ldb, int ldc,
                  int batches, int zInner,
                  long sAo, long sAi, long sBo, long sBi, long sCo, long sCi, long sBias,
                  float alpha, int flags)
{
    dim3 grid(N / BN, M / 128, batches);
    if (BN == 128)
        mma_gemm_k<128><<<grid, 256, 81920>>>(A, B, bias, C, K, lda, ldb, ldc,
            zInner, sAo, sAi, sBo, sBi, sCo, sCi, sBias, alpha, flags);
    else
        mma_gemm_k<64><<<grid, 256, 61440>>>(A, B, bias, C, K, lda, ldb, ldc,
            zInner, sAo, sAi, sBo, sBi, sCo, sCi, sBias, alpha, flags);
}

extern "C" void kernel_launch(void* const* d_in, const int* in_sizes, int n_in,
                              void* d_out, int out_size)
{
    const float* seg   = (const float*)d_in[0];
    const float* mask  = (const float*)d_in[1];
    const float* se    = (const float*)d_in[2];
    const float* hw1   = (const float*)d_in[3];
    const float* hb1   = (const float*)d_in[4];
    const float* hw2   = (const float*)d_in[5];
    const float* hb2   = (const float*)d_in[6];
    const float* hw3   = (const float*)d_in[7];
    const float* hb3   = (const float*)d_in[8];
    const float* lcW   = (const float*)d_in[9];
    const float* lcb   = (const float*)d_in[10];
    const float* lvW   = (const float*)d_in[11];
    const float* lvb   = (const float*)d_in[12];
    const float* gcW   = (const float*)d_in[13];
    const float* gcb   = (const float*)d_in[14];
    const float* gvW   = (const float*)d_in[15];
    const float* gvb   = (const float*)d_in[16];
    const float* sw1   = (const float*)d_in[17];
    const float* sw2   = (const float*)d_in[18];
    float* out = (float*)d_out;

    static int init = 0;
    if (!init) {
        cudaFuncSetAttribute(mma_gemm_k<128>, cudaFuncAttributeMaxDynamicSharedMemorySize, 81920);
        cudaFuncSetAttribute(mma_gemm_k<64>,  cudaFuncAttributeMaxDynamicSharedMemorySize, 61440);
        init = 1;
    }

    float *pB1, *pM, *pCT, *pMK, *pA, *pS;
    cudaGetSymbolAddress((void**)&pB1, g_B1);
    cudaGetSymbolAddress((void**)&pM,  g_M);
    cudaGetSymbolAddress((void**)&pCT, g_CT);
    cudaGetSymbolAddress((void**)&pMK, g_MK);
    cudaGetSymbolAddress((void**)&pA,  g_A);
    cudaGetSymbolAddress((void**)&pS,  g_S);

    const long BLD = (long)Bb * Ll * Dd;    // 4194304
    const int ML = Bb * Ll;                  // 8192

    // 1) h2
    h2_k<<<Bb * Nn, Dd>>>(se, hw2, hb2);

    // 2) h1 = relu(seg @ w1 + b1), batched over n
    mgemm(128, seg, hw1, hb1, pB1, ML, Dd, Dd, Dd, Dd, Dd,
          Nn, Nn, 0, 0, 0, (long)Dd * Dd, 0, BLD, Dd, 1.f, 2);

    // 3) h1 *= h2
    mulh2_k<<<4096, 256>>>();

    // 4) m = relu(h1m @ w3 + b3), batched over n
    mgemm(128, pB1, hw3, hb3, pM, ML, Dd, Dd, Dd, Dd, Dd,
          Nn, Nn, 0, BLD, 0, (long)Dd * Dd, 0, BLD, Dd, 1.f, 2);

    // 5) local non-local blocks: per stage, batched over n
    for (int s = 0; s < 2; s++) {
        mgemm(128, pM, lcW + (long)s * Dd * 2 * Dd, lcb + (long)s * 2 * Dd, pCT,
              ML, 2 * Dd, Dd, Dd, 2 * Dd, 2 * Dd,
              Nn, Nn, 0, BLD, 0, (long)2 * Dd * 2 * Dd, 0, 2 * BLD, (long)2 * 2 * Dd,
              1.f, 0);
        mgemm(128, pM, lvW + (long)s * Dd * Dd, lvb + (long)s * Dd, pMK,
              ML, Dd, Dd, Dd, Dd, Dd,
              Nn, Nn, 0, BLD, 0, (long)2 * Dd * Dd, 0, BLD, (long)2 * Dd,
              1.f, 0);
        local_attn_k<<<Nn * Bb * Ll * Hh * 32 / 128, 128>>>(mask);
    }

    // 6) segment attention weights
    satt_k<<<Bb, AH>>>(se, sw1, sw2, out + BLD);

    // 7) aggregate
    agg_k<<<4096, 256>>>();

    // 8) global non-local blocks
    for (int s = 0; s < 2; s++) {
        mgemm(128, pA, gcW + (long)s * Dd * 2 * Dd, gcb + (long)s * 2 * Dd, pCT,
              ML, 2 * Dd, Dd, Dd, 2 * Dd, 2 * Dd,
              1, 1, 0, 0, 0, 0, 0, 0, 0, 1.f, 0);
        mgemm(128, pA, gvW + (long)s * Dd * Dd, gvb + (long)s * Dd, pMK,
              ML, Dd, Dd, Dd, Dd, Dd,
              1, 1, 0, 0, 0, 0, 0, 0, 0, 1.f, 0);
        // scores: S[b,h] = (mk_bh @ mq_bh^T) / 8
        mgemm(128, pMK, pCT, nullptr, pS,
              Ll, Ll, DH, Dd, 2 * Dd, Ll,
              Bb * Hh, Hh,
              (long)Ll * Dd, DH,
              (long)Ll * 2 * Dd, DH,
              (long)Hh * Ll * Ll, (long)Ll * Ll, 0,
              0.125f, 1);
        softmax_k<<<Bb * Hh * Ll, 256>>>(pS, mask);
        // out: X[b,:,h*64:] += W[b,h] @ mv_bh
        mgemm(64, pS, pCT + Dd, nullptr, pA,
              Ll, DH, Ll, Ll, 2 * Dd, Dd,
              Bb * Hh, Hh,
              (long)Hh * Ll * Ll, (long)Ll * Ll,
              (long)Ll * 2 * Dd, DH,
              (long)Ll * Dd, DH, 0,
              1.f, 4);
    }

    // 9) output
    copyout_k<<<4096, 256>>>(out);
}

// round 4
// speedup vs baseline: 1.9378x; 1.0044x over previous
#include <cuda_runtime.h>
#include <cuda_bf16.h>
#include <math.h>
#include <stdint.h>

#define Bb 16
#define Ll 512
#define Dd 512
#define Nn 3
#define Hh 8
#define DH 64
#define AH 256
#define KHALF 7

#define BLD 4194304L   // Bb*Ll*Dd

// ---------------- scratch: all GEMM tensors as (hi,lo) bf16 pairs -------------
__device__ __nv_bfloat16 g_segH[BLD],      g_segL[BLD];
__device__ __nv_bfloat16 g_WH[7864320],    g_WL[7864320];
__device__ __nv_bfloat16 g_B1H[3*BLD],     g_B1L[3*BLD];
__device__ __nv_bfloat16 g_MH [3*BLD],     g_ML [3*BLD];
__device__ __nv_bfloat16 g_CTH[6*BLD],     g_CTL[6*BLD];     // [n][8192][1024]
__device__ __nv_bfloat16 g_MKH[3*BLD],     g_MKL[3*BLD];
__device__ __nv_bfloat16 g_AHb[BLD],       g_ALb[BLD];
__device__ __nv_bfloat16 g_SH [(long)Bb*Hh*Ll*Ll], g_SL[(long)Bb*Hh*Ll*Ll];
__device__ float g_H2[Bb*Nn*Dd];
__device__ float g_SW[Bb*Nn];

// weight region offsets (elements)
#define OFF_HW1 0L
#define OFF_HW3 786432L
#define OFF_LCW 1572864L
#define OFF_LVW 4718592L
#define OFF_GCW 6291456L
#define OFF_GVW 7340032L

// ---------------- PTX helpers -------------------------------------------------
__device__ __forceinline__ uint32_t smem_u32(const void* p) {
    uint32_t a;
    asm("{ .reg .u64 t; cvta.to.shared.u64 t, %1; cvt.u32.u64 %0, t; }" : "=r"(a) : "l"(p));
    return a;
}
#define CPA16(dst, src) asm volatile( \
    "cp.async.ca.shared.global [%0], [%1], 16;" :: "r"(dst), "l"(__cvta_generic_to_global(src)))
#define CPA_COMMIT() asm volatile("cp.async.commit_group;" ::: "memory")
#define CPA_WAIT1()  asm volatile("cp.async.wait_group 1;" ::: "memory")

#define LDM_X4(r, a) asm volatile( \
    "ldmatrix.sync.aligned.m8n8.x4.shared.b16 {%0,%1,%2,%3}, [%4];" \
    : "=r"((r)[0]),"=r"((r)[1]),"=r"((r)[2]),"=r"((r)[3]) : "r"(a))
#define LDM_X4T(r, a) asm volatile( \
    "ldmatrix.sync.aligned.m8n8.x4.trans.shared.b16 {%0,%1,%2,%3}, [%4];" \
    : "=r"((r)[0]),"=r"((r)[1]),"=r"((r)[2]),"=r"((r)[3]) : "r"(a))
#define MMA16816(d, a, b) asm volatile( \
    "mma.sync.aligned.m16n8k16.row.col.f32.bf16.bf16.f32 " \
    "{%0,%1,%2,%3}, {%4,%5,%6,%7}, {%8,%9}, {%0,%1,%2,%3};" \
    : "+f"((d)[0]),"+f"((d)[1]),"+f"((d)[2]),"+f"((d)[3]) \
    : "r"((a)[0]),"r"((a)[1]),"r"((a)[2]),"r"((a)[3]), "r"((b)[0]),"r"((b)[1]))

__device__ __forceinline__ float bfadd(__nv_bfloat16 h, __nv_bfloat16 l) {
    return __bfloat162float(h) + __bfloat162float(l);
}
__device__ __forceinline__ void bfsplit(float v, __nv_bfloat16& h, __nv_bfloat16& l) {
    h = __float2bfloat16(v);
    l = __float2bfloat16(v - __bfloat162float(h));
}

// ---------------- fp32 -> (hi,lo) split prepass -------------------------------
__global__ void split_k(const float* __restrict__ s, __nv_bfloat16* __restrict__ h,
                        __nv_bfloat16* __restrict__ l, long n)
{
    for (long i = ((long)blockIdx.x * blockDim.x + threadIdx.x) * 4; i < n;
         i += (long)gridDim.x * blockDim.x * 4) {
        float4 v = *reinterpret_cast<const float4*>(s + i);
        __nv_bfloat16 hh[4], ll[4];
        bfsplit(v.x, hh[0], ll[0]); bfsplit(v.y, hh[1], ll[1]);
        bfsplit(v.z, hh[2], ll[2]); bfsplit(v.w, hh[3], ll[3]);
        *reinterpret_cast<uint2*>(h + i) = *reinterpret_cast<uint2*>(hh);
        *reinterpret_cast<uint2*>(l + i) = *reinterpret_cast<uint2*>(ll);
    }
}

// ---------------- bf16-split mma.sync GEMM with cp.async pipeline -------------
// C = act( alpha * A @ op(B) + bias ) (+C if beta1); all of A,B,C are (hi,lo) pairs
// flags: 1=transB (B is [N][K]), 2=relu, 4=accumulate
template<int BN_T>
__global__ void __launch_bounds__(256, 1) mma_gemm_k(
    const __nv_bfloat16* __restrict__ Ah, const __nv_bfloat16* __restrict__ Al,
    const __nv_bfloat16* __restrict__ Bh, const __nv_bfloat16* __restrict__ Bl,
    const float* __restrict__ bias,
    __nv_bfloat16* __restrict__ Ch, __nv_bfloat16* __restrict__ Cl,
    int K, int lda, int ldb, int ldc, int zInner,
    long sAo, long sAi, long sBo, long sBi, long sCo, long sCi, long sBias,
    float alpha, int flags)
{
    constexpr int BK = 32, LDS = 40;
    constexpr int LDSB = BN_T + 8;
    constexpr int WN = BN_T / 4;
    constexpr int NT = WN / 8;
    constexpr int MT = 4;
    constexpr int A_BYTES = 128 * LDS * 2;                     // 10240
    constexpr int B_NTB = BK * LDSB * 2;                       // !tb bytes
    constexpr int B_TB  = BN_T * LDS * 2;                      // tb bytes
    constexpr int B_BYTES = (B_NTB > B_TB) ? B_NTB : B_TB;
    constexpr int STAGE = 2 * A_BYTES + 2 * B_BYTES;
    constexpr int BIT = BN_T / 64;                             // B fill iters

    extern __shared__ char dsm[];
    uint32_t sb0 = smem_u32(dsm);

    int z = blockIdx.z, zo = z / zInner, zi = z % zInner;
    Ah += zo * sAo + zi * sAi;  Al += zo * sAo + zi * sAi;
    Bh += zo * sBo + zi * sBi;  Bl += zo * sBo + zi * sBi;
    Ch += zo * sCo + zi * sCi;  Cl += zo * sCo + zi * sCi;
    if (bias) bias += zi * sBias;

    int tid = threadIdx.x, lane = tid & 31, wid = tid >> 5;
    int wm = wid & 1, wn = wid >> 1;
    int m0 = blockIdx.y * 128, n0 = blockIdx.x * BN_T;
    const bool tb = flags & 1;
    int nc = K / BK;

    auto fill = [&](int c) {
        int k0 = c * BK;
        uint32_t st = sb0 + (c % 3) * STAGE;
        #pragma unroll
        for (int it = 0; it < 2; it++) {                       // A hi/lo
            int idx = tid + it * 256;
            int row = idx >> 2, u = idx & 3;
            uint32_t d = st + row * (LDS * 2) + u * 16;
            long g = (long)(m0 + row) * lda + k0 + u * 8;
            CPA16(d, Ah + g);
            CPA16(d + A_BYTES, Al + g);
        }
        if (!tb) {
            #pragma unroll
            for (int it = 0; it < BIT; it++) {
                int idx = tid + it * 256;
                int kk = idx / (BN_T / 8), u = idx % (BN_T / 8);
                uint32_t d = st + 2 * A_BYTES + (kk * LDSB + u * 8) * 2;
                long g = (long)(k0 + kk) * ldb + n0 + u * 8;
                CPA16(d, Bh + g);
                CPA16(d + B_BYTES, Bl + g);
            }
        } else {
            #pragma unroll
            for (int it = 0; it < BIT; it++) {
                int idx = tid + it * 256;
                int nn = idx >> 2, u = idx & 3;
                uint32_t d = st + 2 * A_BYTES + (nn * LDS + u * 8) * 2;
                long g = (long)(n0 + nn) * ldb + k0 + u * 8;
                CPA16(d, Bh + g);
                CPA16(d + B_BYTES, Bl + g);
            }
        }
    };

    float acc[MT][NT][4];
    #pragma unroll
    for (int i = 0; i < MT; i++)
        #pragma unroll
        for (int j = 0; j < NT; j++)
            #pragma unroll
            for (int e = 0; e < 4; e++) acc[i][j][e] = 0.f;

    fill(0); CPA_COMMIT();
    fill(1); CPA_COMMIT();

    // ldmatrix lane offsets
    int alr = lane & 15, alc = (lane >> 4) << 3;
    int blr = (lane & 7) + (((lane >> 4) & 1) << 3);   // tb
    int blc = ((lane >> 3) & 1) << 3;
    int btr = (lane & 7) + (((lane >> 3) & 1) << 3);   // !tb (trans ldm)
    int btc = ((lane >> 4) & 1) << 3;

    for (int c = 0; c < nc; c++) {
        CPA_WAIT1();
        __syncthreads();
        if (c + 2 < nc) fill(c + 2);
        CPA_COMMIT();

        uint32_t base = sb0 + (c % 3) * STAGE;
        uint32_t aAhi = base + ((wm * 64 + alr) * LDS + alc) * 2;

        #pragma unroll
        for (int kk = 0; kk < 2; kk++) {
            uint32_t ah[MT][4], al[MT][4], bh[NT][2], bl[NT][2];
            #pragma unroll
            for (int mt = 0; mt < MT; mt++) {
                uint32_t o = (uint32_t)((mt * 16 * LDS + kk * 16) * 2);
                LDM_X4(ah[mt], aAhi + o);
                LDM_X4(al[mt], aAhi + A_BYTES + o);
            }
            if (!tb) {
                uint32_t aB = base + 2 * A_BYTES +
                              (uint32_t)(((kk * 16 + btr) * LDSB + wn * WN + btc) * 2);
                #pragma unroll
                for (int p = 0; p < NT / 2; p++) {
                    uint32_t o = (uint32_t)(p * 16 * 2);
                    uint32_t r[4];
                    LDM_X4T(r, aB + o);
                    bh[2*p][0]=r[0]; bh[2*p][1]=r[1]; bh[2*p+1][0]=r[2]; bh[2*p+1][1]=r[3];
                    LDM_X4T(r, aB + B_BYTES + o);
                    bl[2*p][0]=r[0]; bl[2*p][1]=r[1]; bl[2*p+1][0]=r[2]; bl[2*p+1][1]=r[3];
                }
            } else {
                uint32_t aB = base + 2 * A_BYTES +
                              (uint32_t)(((wn * WN + blr) * LDS + kk * 16 + blc) * 2);
                #pragma unroll
                for (int p = 0; p < NT / 2; p++) {
                    uint32_t o = (uint32_t)(p * 16 * LDS * 2);
                    uint32_t r[4];
                    LDM_X4(r, aB + o);
                    bh[2*p][0]=r[0]; bh[2*p][1]=r[1]; bh[2*p+1][0]=r[2]; bh[2*p+1][1]=r[3];
                    LDM_X4(r, aB + B_BYTES + o);
                    bl[2*p][0]=r[0]; bl[2*p][1]=r[1]; bl[2*p+1][0]=r[2]; bl[2*p+1][1]=r[3];
                }
            }
            #pragma unroll
            for (int mt = 0; mt < MT; mt++)
                #pragma unroll
                for (int nt = 0; nt < NT; nt++) {
                    MMA16816(acc[mt][nt], ah[mt], bh[nt]);
                    MMA16816(acc[mt][nt], ah[mt], bl[nt]);
                    MMA16816(acc[mt][nt], al[mt], bh[nt]);
                }
        }
    }

    // ---- epilogue: fp32 math, write (hi,lo) pairs
    #pragma unroll
    for (int mt = 0; mt < MT; mt++) {
        int row = m0 + wm * 64 + mt * 16 + (lane >> 2);
        #pragma unroll
        for (int nt = 0; nt < NT; nt++) {
            int col = n0 + wn * WN + nt * 8 + (lane & 3) * 2;
            float d0 = acc[mt][nt][0] * alpha, d1 = acc[mt][nt][1] * alpha;
            float d2 = acc[mt][nt][2] * alpha, d3 = acc[mt][nt][3] * alpha;
            if (bias) {
                float b0 = bias[col], b1 = bias[col + 1];
                d0 += b0; d1 += b1; d2 += b0; d3 += b1;
            }
            if (flags & 2) {
                d0 = fmaxf(d0, 0.f); d1 = fmaxf(d1, 0.f);
                d2 = fmaxf(d2, 0.f); d3 = fmaxf(d3, 0.f);
            }
            long o0 = (long)row * ldc + col;
            long o1 = o0 + (long)8 * ldc;
            if (flags & 4) {
                __nv_bfloat162 h0 = *reinterpret_cast<const __nv_bfloat162*>(Ch + o0);
                __nv_bfloat162 l0 = *reinterpret_cast<const __nv_bfloat162*>(Cl + o0);
                __nv_bfloat162 h1 = *reinterpret_cast<const __nv_bfloat162*>(Ch + o1);
                __nv_bfloat162 l1 = *reinterpret_cast<const __nv_bfloat162*>(Cl + o1);
                d0 += bfadd(h0.x, l0.x); d1 += bfadd(h0.y, l0.y);
                d2 += bfadd(h1.x, l1.x); d3 += bfadd(h1.y, l1.y);
            }
            __nv_bfloat16 h[4], l[4];
            bfsplit(d0, h[0], l[0]); bfsplit(d1, h[1], l[1]);
            bfsplit(d2, h[2], l[2]); bfsplit(d3, h[3], l[3]);
            *reinterpret_cast<__nv_bfloat162*>(Ch + o0) = __nv_bfloat162{h[0], h[1]};
            *reinterpret_cast<__nv_bfloat162*>(Cl + o0) = __nv_bfloat162{l[0], l[1]};
            *reinterpret_cast<__nv_bfloat162*>(Ch + o1) = __nv_bfloat162{h[2], h[3]};
            *reinterpret_cast<__nv_bfloat162*>(Cl + o1) = __nv_bfloat162{l[2], l[3]};
        }
    }
}

// ---------------- small kernels ------------------------------------------------
__global__ void h2_k(const float* __restrict__ se, const float* __restrict__ w2,
                     const float* __restrict__ b2)
{
    int bn = blockIdx.x;
    int n = bn % Nn;
    int h = threadIdx.x;
    const float* x = se + (long)bn * Dd;
    const float* w = w2 + (long)n * Dd * Dd;
    float acc = b2[n * Dd + h];
    for (int d = 0; d < Dd; d++) acc = fmaf(x[d], w[(long)d * Dd + h], acc);
    g_H2[(long)bn * Dd + h] = fmaxf(acc, 0.f);
}

__global__ void mulh2_k()
{
    long total = 3 * BLD;
    for (long i = (long)blockIdx.x * blockDim.x + threadIdx.x; i < total;
         i += (long)gridDim.x * blockDim.x) {
        int h = (int)(i % Dd);
        long r = i / Dd;
        int b = (int)((r / Ll) % Bb);
        int n = (int)(r / ((long)Ll * Bb));
        float v = bfadd(g_B1H[i], g_B1L[i]) * g_H2[((long)b * Nn + n) * Dd + h];
        bfsplit(v, g_B1H[i], g_B1L[i]);
    }
}

// banded local attention + residual; warp per (n,b,l,h); operands in (hi,lo)
__global__ void local_attn_k(const float* __restrict__ mask)
{
    int gw = (int)(((long)blockIdx.x * blockDim.x + threadIdx.x) >> 5);
    int lane = threadIdx.x & 31;
    if (gw >= Nn * Bb * Ll * Hh) return;
    int h = gw % Hh;
    int l = (gw / Hh) % Ll;
    int b = (gw / (Hh * Ll)) % Bb;
    int n = gw / (Hh * Ll * Bb);

    const __nv_bfloat16* MKH_ = g_MKH + (long)n * BLD;
    const __nv_bfloat16* MKL_ = g_MKL + (long)n * BLD;
    const __nv_bfloat16* CTH_ = g_CTH + (long)n * 2 * BLD;
    const __nv_bfloat16* CTL_ = g_CTL + (long)n * 2 * BLD;

    long ko = ((long)b * Ll + l) * Dd + h * DH;
    float k0 = bfadd(MKH_[ko + lane], MKL_[ko + lane]);
    float k1 = bfadd(MKH_[ko + lane + 32], MKL_[ko + lane + 32]);

    float sc[15];
    #pragma unroll
    for (int j = 0; j < 15; j++) {
        int m = l + (j - KHALF);
        float s = -1e30f;
        if (m >= 0 && m < Ll && mask[(long)b * Ll + m] != 0.f) {
            long mo = ((long)b * Ll + m) * (2 * Dd) + h * DH;
            float q0 = bfadd(CTH_[mo + lane], CTL_[mo + lane]);
            float q1 = bfadd(CTH_[mo + lane + 32], CTL_[mo + lane + 32]);
            float d = k0 * q0 + k1 * q1;
            #pragma unroll
            for (int o = 16; o; o >>= 1) d += __shfl_xor_sync(0xffffffffu, d, o);
            s = d * 0.125f;
        }
        sc[j] = s;
    }
    float mx = -1e30f;
    #pragma unroll
    for (int j = 0; j < 15; j++) mx = fmaxf(mx, sc[j]);
    float w[15], sum = 0.f;
    #pragma unroll
    for (int j = 0; j < 15; j++) {
        w[j] = (sc[j] > -1e29f) ? expf(sc[j] - mx) : 0.f;
        sum += w[j];
    }
    float inv = 1.f / sum;
    float o0 = 0.f, o1 = 0.f;
    #pragma unroll
    for (int j = 0; j < 15; j++) {
        if (w[j] != 0.f) {
            int m = l + (j - KHALF);
            long mo = ((long)b * Ll + m) * (2 * Dd) + Dd + h * DH;
            float ww = w[j] * inv;
            o0 = fmaf(ww, bfadd(CTH_[mo + lane], CTL_[mo + lane]), o0);
            o1 = fmaf(ww, bfadd(CTH_[mo + lane + 32], CTL_[mo + lane + 32]), o1);
        }
    }
    __nv_bfloat16* XH = g_MH + (long)n * BLD + ko;
    __nv_bfloat16* XL = g_ML + (long)n * BLD + ko;
    float x0 = bfadd(XH[lane], XL[lane]) + o0;
    float x1 = bfadd(XH[lane + 32], XL[lane + 32]) + o1;
    bfsplit(x0, XH[lane], XL[lane]);
    bfsplit(x1, XH[lane + 32], XL[lane + 32]);
}

__global__ void softmax_k(const float* __restrict__ mask)
{
    long row = blockIdx.x;
    int b = (int)(row / ((long)Hh * Ll));
    __nv_bfloat16* sh = g_SH + row * Ll;
    __nv_bfloat16* sl = g_SL + row * Ll;
    const float* mrow = mask + (long)b * Ll;
    int t = threadIdx.x;

    float v0 = (mrow[t]       != 0.f) ? bfadd(sh[t], sl[t])             : -1e9f;
    float v1 = (mrow[t + 256] != 0.f) ? bfadd(sh[t + 256], sl[t + 256]) : -1e9f;

    __shared__ float red[256];
    red[t] = fmaxf(v0, v1);
    __syncthreads();
    for (int o = 128; o; o >>= 1) { if (t < o) red[t] = fmaxf(red[t], red[t + o]); __syncthreads(); }
    float mx = red[0];
    __syncthreads();

    float e0 = expf(v0 - mx), e1 = expf(v1 - mx);
    red[t] = e0 + e1;
    __syncthreads();
    for (int o = 128; o; o >>= 1) { if (t < o) red[t] += red[t + o]; __syncthreads(); }
    float inv = 1.f / red[0];
    bfsplit(e0 * inv, sh[t], sl[t]);
    bfsplit(e1 * inv, sh[t + 256], sl[t + 256]);
}

__global__ void satt_k(const float* __restrict__ se, const float* __restrict__ w1,
                       const float* __restrict__ w2, float* __restrict__ out_tail)
{
    int b = blockIdx.x, t = threadIdx.x;
    __shared__ float red[256];
    __shared__ float alpha[Nn];
    for (int n = 0; n < Nn; n++) {
        const float* x = se + ((long)b * Nn + n) * Dd;
        float acc = 0.f;
        for (int d = 0; d < Dd; d++) acc = fmaf(x[d], w1[(long)d * AH + t], acc);
        red[t] = tanhf(acc) * w2[t];
        __syncthreads();
        for (int o = 128; o; o >>= 1) { if (t < o) red[t] += red[t + o]; __syncthreads(); }
        if (t == 0) alpha[n] = red[0];
        __syncthreads();
    }
    if (t == 0) {
        float mx = fmaxf(alpha[0], fmaxf(alpha[1], alpha[2]));
        float e[Nn], sum = 0.f;
        for (int n = 0; n < Nn; n++) { e[n] = expf(alpha[n] - mx); sum += e[n]; }
        for (int n = 0; n < Nn; n++) {
            float w = e[n] / sum;
            g_SW[b * Nn + n] = w;
            out_tail[b * Nn + n] = w;
        }
    }
}

__global__ void agg_k()
{
    long stride = (long)Ll * Dd;
    for (long i = (long)blockIdx.x * blockDim.x + threadIdx.x; i < BLD;
         i += (long)gridDim.x * blockDim.x) {
        int b = (int)(i / stride);
        float acc = 0.f;
        #pragma unroll
        for (int n = 0; n < Nn; n++)
            acc = fmaf(g_SW[b * Nn + n], bfadd(g_MH[(long)n * BLD + i], g_ML[(long)n * BLD + i]), acc);
        bfsplit(acc, g_AHb[i], g_ALb[i]);
    }
}

__global__ void copyout_k(float* __restrict__ out)
{
    for (long i = (long)blockIdx.x * blockDim.x + threadIdx.x; i < BLD;
         i += (long)gridDim.x * blockDim.x)
        out[i] = bfadd(g_AHb[i], g_ALb[i]);
}

// ---------------- host orchestration ------------------------------------------
static void mgemm(int BN, const __nv_bfloat16* Ah, const __nv_bfloat16* Al,
                  const __nv_bfloat16* Bh, const __nv_bfloat16* Bl,
                  const float* bias, __nv_bfloat16* Ch, __nv_bfloat16* Cl,
                  int M, int N, int K, int lda, int ldb, int ldc,
                  int batches, int zInner,
                  long sAo, long sAi, long sBo, long sBi, long sCo, long sCi, long sBias,
                  float alpha, int flags)
{
    dim3 grid(N / BN, M / 128, batches);
    if (BN == 128)
        mma_gemm_k<128><<<grid, 256, 122880>>>(Ah, Al, Bh, Bl, bias, Ch, Cl, K,
            lda, ldb, ldc, zInner, sAo, sAi, sBo, sBi, sCo, sCi, sBias, alpha, flags);
    else
        mma_gemm_k<64><<<grid, 256, 92160>>>(Ah, Al, Bh, Bl, bias, Ch, Cl, K,
            lda, ldb, ldc, zInner, sAo, sAi, sBo, sBi, sCo, sCi, sBias, alpha, flags);
}

extern "C" void kernel_launch(void* const* d_in, const int* in_sizes, int n_in,
                              void* d_out, int out_size)
{
    const float* seg   = (const float*)d_in[0];
    const float* mask  = (const float*)d_in[1];
    const float* se    = (const float*)d_in[2];
    const float* hw1   = (const float*)d_in[3];
    const float* hb1   = (const float*)d_in[4];
    const float* hw2   = (const float*)d_in[5];
    const float* hb2   = (const float*)d_in[6];
    const float* hw3   = (const float*)d_in[7];
    const float* hb3   = (const float*)d_in[8];
    const float* lcW   = (const float*)d_in[9];
    const float* lcb   = (const float*)d_in[10];
    const float* lvW   = (const float*)d_in[11];
    const float* lvb   = (const float*)d_in[12];
    const float* gcW   = (const float*)d_in[13];
    const float* gcb   = (const float*)d_in[14];
    const float* gvW   = (const float*)d_in[15];
    const float* gvb   = (const float*)d_in[16];
    const float* sw1   = (const float*)d_in[17];
    const float* sw2   = (const float*)d_in[18];
    float* out = (float*)d_out;

    cudaFuncSetAttribute(mma_gemm_k<128>, cudaFuncAttributeMaxDynamicSharedMemorySize, 122880);
    cudaFuncSetAttribute(mma_gemm_k<64>,  cudaFuncAttributeMaxDynamicSharedMemorySize, 92160);

    __nv_bfloat16 *pSegH, *pSegL, *pWH, *pWL, *pB1H, *pB1L, *pMH, *pML,
                  *pCTH, *pCTL, *pMKH, *pMKL, *pAH, *pAL, *pSH, *pSL;
    cudaGetSymbolAddress((void**)&pSegH, g_segH); cudaGetSymbolAddress((void**)&pSegL, g_segL);
    cudaGetSymbolAddress((void**)&pWH, g_WH);     cudaGetSymbolAddress((void**)&pWL, g_WL);
    cudaGetSymbolAddress((void**)&pB1H, g_B1H);   cudaGetSymbolAddress((void**)&pB1L, g_B1L);
    cudaGetSymbolAddress((void**)&pMH, g_MH);     cudaGetSymbolAddress((void**)&pML, g_ML);
    cudaGetSymbolAddress((void**)&pCTH, g_CTH);   cudaGetSymbolAddress((void**)&pCTL, g_CTL);
    cudaGetSymbolAddress((void**)&pMKH, g_MKH);   cudaGetSymbolAddress((void**)&pMKL, g_MKL);
    cudaGetSymbolAddress((void**)&pAH, g_AHb);    cudaGetSymbolAddress((void**)&pAL, g_ALb);
    cudaGetSymbolAddress((void**)&pSH, g_SH);     cudaGetSymbolAddress((void**)&pSL, g_SL);

    const int ML_ = Bb * Ll;   // 8192

    // ---- split prepasses
    split_k<<<1024, 256>>>(seg, pSegH, pSegL, BLD);
    split_k<<<512, 256>>>(hw1, pWH + OFF_HW1, pWL + OFF_HW1, 786432);
    split_k<<<512, 256>>>(hw3, pWH + OFF_HW3, pWL + OFF_HW3, 786432);
    split_k<<<1024, 256>>>(lcW, pWH + OFF_LCW, pWL + OFF_LCW, 3145728);
    split_k<<<1024, 256>>>(lvW, pWH + OFF_LVW, pWL + OFF_LVW, 1572864);
    split_k<<<512, 256>>>(gcW, pWH + OFF_GCW, pWL + OFF_GCW, 1048576);
    split_k<<<512, 256>>>(gvW, pWH + OFF_GVW, pWL + OFF_GVW, 524288);

    // 1) h2
    h2_k<<<Bb * Nn, Dd>>>(se, hw2, hb2);

    // 2) h1 = relu(seg @ w1 + b1), batched over n
    mgemm(128, pSegH, pSegL, pWH + OFF_HW1, pWL + OFF_HW1, hb1, pB1H, pB1L,
          ML_, Dd, Dd, Dd, Dd, Dd, Nn, Nn,
          0, 0, 0, (long)Dd * Dd, 0, BLD, Dd, 1.f, 2);

    // 3) h1 *= h2
    mulh2_k<<<4096, 256>>>();

    // 4) m = relu(h1m @ w3 + b3)
    mgemm(128, pB1H, pB1L, pWH + OFF_HW3, pWL + OFF_HW3, hb3, pMH, pML,
          ML_, Dd, Dd, Dd, Dd, Dd, Nn, Nn,
          0, BLD, 0, (long)Dd * Dd, 0, BLD, Dd, 1.f, 2);

    // 5) local non-local blocks: per stage, batched over n
    for (int s = 0; s < 2; s++) {
        mgemm(128, pMH, pML, pWH + OFF_LCW + (long)s * Dd * 2 * Dd,
              pWL + OFF_LCW + (long)s * Dd * 2 * Dd, lcb + (long)s * 2 * Dd, pCTH, pCTL,
              ML_, 2 * Dd, Dd, Dd, 2 * Dd, 2 * Dd, Nn, Nn,
              0, BLD, 0, (long)2 * Dd * 2 * Dd, 0, 2 * BLD, (long)2 * 2 * Dd, 1.f, 0);
        mgemm(128, pMH, pML, pWH + OFF_LVW + (long)s * Dd * Dd,
              pWL + OFF_LVW + (long)s * Dd * Dd, lvb + (long)s * Dd, pMKH, pMKL,
              ML_, Dd, Dd, Dd, Dd, Dd, Nn, Nn,
              0, BLD, 0, (long)2 * Dd * Dd, 0, BLD, (long)2 * Dd, 1.f, 0);
        local_attn_k<<<Nn * Bb * Ll * Hh * 32 / 128, 128>>>(mask);
    }

    // 6) segment attention weights
    satt_k<<<Bb, AH>>>(se, sw1, sw2, out + BLD);

    // 7) aggregate
    agg_k<<<4096, 256>>>();

    // 8) global non-local blocks
    for (int s = 0; s < 2; s++) {
        mgemm(128, pAH, pAL, pWH + OFF_GCW + (long)s * Dd * 2 * Dd,
              pWL + OFF_GCW + (long)s * Dd * 2 * Dd, gcb + (long)s * 2 * Dd, pCTH, pCTL,
              ML_, 2 * Dd, Dd, Dd, 2 * Dd, 2 * Dd, 1, 1,
              0, 0, 0, 0, 0, 0, 0, 1.f, 0);
        mgemm(128, pAH, pAL, pWH + OFF_GVW + (long)s * Dd * Dd,
              pWL + OFF_GVW + (long)s * Dd * Dd, gvb + (long)s * Dd, pMKH, pMKL,
              ML_, Dd, Dd, Dd, Dd, Dd, 1, 1,
              0, 0, 0, 0, 0, 0, 0, 1.f, 0);
        // scores: S[b,h] = (mk_bh @ mq_bh^T) / 8
        mgemm(128, pMKH, pMKL, pCTH, pCTL, nullptr, pSH, pSL,
              Ll, Ll, DH, Dd, 2 * Dd, Ll, Bb * Hh, Hh,
              (long)Ll * Dd, DH,
              (long)Ll * 2 * Dd, DH,
              (long)Hh * Ll * Ll, (long)Ll * Ll, 0,
              0.125f, 1);
        softmax_k<<<Bb * Hh * Ll, 256>>>(mask);
        // out: A[b,:,h*64:] += W[b,h] @ mv_bh
        mgemm(64, pSH, pSL, pCTH + Dd, pCTL + Dd, nullptr, pAH, pAL,
              Ll, DH, Ll, Ll, 2 * Dd, Dd, Bb * Hh, Hh,
              (long)Hh * Ll * Ll, (long)Ll * Ll,
              (long)Ll * 2 * Dd, DH,
              (long)Ll * Dd, DH, 0,
              1.f, 4);
    }

    // 9) output
    copyout_k<<<4096, 256>>>(out);
}